// round 4
// baseline (speedup 1.0000x reference)
#include <cuda_runtime.h>
#include <cstdint>

// ------------------------- problem constants -------------------------------
#define NROWS 65536
#define DIM   256
#define KCODE 1024
#define ND    (NROWS * DIM)
#define DELTA 2.0e-4f            // margin threshold for exact repair

// ------------------------- tiling ------------------------------------------
#define BM   128                 // rows per CTA panel
#define BN   128                 // codes per code-tile
#define NCT  (KCODE / BN)        // 8 code-tiles
#define KC   32                  // d per staged chunk
#define NCHT (NCT * (DIM / KC))  // 64 total chunks per panel
#define NT   256                 // threads (8 warps: 4 x warp_m, 2 x warp_n)
#define GRID (NROWS / BM)        // 512 CTAs

// ------------------------- scratch globals ---------------------------------
__device__ __align__(16) float g_ne[KCODE];
__device__ __align__(16) float g_eh[KCODE * DIM];   // tf32-hi of embedding
__device__ __align__(16) float g_el[KCODE * DIM];   // tf32-lo residual
__device__ int   g_idx[NROWS];
__device__ float g_part[16384];
__device__ int   g_list[NROWS];                     // marginal rows
__device__ int   g_cnt;

// ------------------------- smem layout (float indices) ---------------------
#define AS_STR 260
#define AS_OFF 0
#define AS_FLT (BM * AS_STR)
#define BS_STR 36
#define BS_OFF AS_FLT
#define BS_BUF (2 * BN * BS_STR)
#define NE_OFF (BS_OFF + 2 * BS_BUF)
#define NX_OFF (NE_OFF + KCODE)
#define RV_OFF (NX_OFF + BM)             // [2][128] best val
#define RI_OFF (RV_OFF + 2 * BM)         // [2][128] best idx
#define R2_OFF (RI_OFF + 2 * BM)         // [2][128] second-best val
#define SM_FLT (R2_OFF + 2 * BM)
#define SMEM_BYTES (SM_FLT * 4)

// ------------------------- ptx helpers (sm_80-portable only) ----------------
__device__ __forceinline__ uint32_t smem_u32(const void* p) {
    uint32_t a;
    asm("{ .reg .u64 t; cvta.to.shared.u64 t, %1; cvt.u32.u64 %0, t; }" : "=r"(a) : "l"(p));
    return a;
}
__device__ __forceinline__ uint32_t tf32_rna(float x) {
    uint32_t u;
    asm("cvt.rna.tf32.f32 %0, %1;" : "=r"(u) : "f"(x));
    return u;
}
__device__ __forceinline__ void cp16(uint32_t saddr, const void* g) {
    asm volatile("cp.async.ca.shared.global [%0], [%1], 16;" :: "r"(saddr), "l"(g) : "memory");
}
#define CP_COMMIT() asm volatile("cp.async.commit_group;" ::: "memory")
#define CP_WAIT1()  asm volatile("cp.async.wait_group 1;" ::: "memory")

__device__ __forceinline__ void mma8(float* c, const uint32_t* a, uint32_t b0, uint32_t b1) {
    asm volatile(
        "mma.sync.aligned.m16n8k8.row.col.f32.tf32.tf32.f32 "
        "{%0,%1,%2,%3},{%4,%5,%6,%7},{%8,%9},{%0,%1,%2,%3};"
        : "+f"(c[0]), "+f"(c[1]), "+f"(c[2]), "+f"(c[3])
        : "r"(a[0]), "r"(a[1]), "r"(a[2]), "r"(a[3]), "r"(b0), "r"(b1));
}

// ===========================================================================
// prep: codebook norms (R1-exact numerics) + tf32 hi/lo split
// ===========================================================================
__global__ void k_ne(const float* __restrict__ emb) {
    if (blockIdx.x == 0 && threadIdx.x == 0) g_cnt = 0;
    int c = blockIdx.x * blockDim.x + threadIdx.x;
    if (c < KCODE) {
        const float* e = emb + (size_t)c * DIM;
        float s = 0.0f;
        #pragma unroll 8
        for (int d = 0; d < DIM; d++) s = __fadd_rn(s, __fmul_rn(e[d], e[d]));
        g_ne[c] = s;
    }
}

__global__ __launch_bounds__(256)
void k_prep(const float* __restrict__ emb) {
    int i = blockIdx.x * 256 + threadIdx.x;
    float4 v = reinterpret_cast<const float4*>(emb)[i];
    uint4 h, l;
    h.x = tf32_rna(v.x); l.x = tf32_rna(__fsub_rn(v.x, __uint_as_float(h.x)));
    h.y = tf32_rna(v.y); l.y = tf32_rna(__fsub_rn(v.y, __uint_as_float(h.y)));
    h.z = tf32_rna(v.z); l.z = tf32_rna(__fsub_rn(v.z, __uint_as_float(h.z)));
    h.w = tf32_rna(v.w); l.w = tf32_rna(__fsub_rn(v.w, __uint_as_float(h.w)));
    reinterpret_cast<uint4*>(g_eh)[i] = h;
    reinterpret_cast<uint4*>(g_el)[i] = l;
}

// ===========================================================================
// fast pass: 3xTF32 mma.sync GEMM + argmin + second-best margin
// ===========================================================================
__global__ __launch_bounds__(NT, 1)
void k_gemm(const float* __restrict__ x) {
    extern __shared__ float sm[];
    const uint32_t sb  = smem_u32(sm);
    const int tid  = threadIdx.x;
    const int lane = tid & 31;
    const int wid  = tid >> 5;
    const int g    = lane >> 2;
    const int tig  = lane & 3;
    const int m0   = (wid & 3) * 32;
    const int n0w  = (wid >> 2) * 64;
    const int wn   = wid >> 2;
    const int rbase = blockIdx.x * BM;

    // ---- prologue: A panel + B chunks 0/1 ----------------------------------
    {
        const float* xp = x + (size_t)rbase * DIM;
        #pragma unroll
        for (int it = 0; it < 32; it++) {
            int idx = tid + it * NT;
            int r = idx >> 6, c4 = idx & 63;
            cp16(sb + (AS_OFF + r * AS_STR + c4 * 4) * 4, xp + r * DIM + c4 * 4);
        }
    }
    {
        int n = tid >> 3, f = tid & 7;
        #pragma unroll
        for (int it = 0; it < 4; it++) {
            int nn = n + it * 32;
            uint32_t dh = sb + (BS_OFF + nn * BS_STR + f * 4) * 4;
            cp16(dh, g_eh + (size_t)nn * DIM + f * 4);
            cp16(dh + BN * BS_STR * 4, g_el + (size_t)nn * DIM + f * 4);
        }
    }
    CP_COMMIT();
    {
        int n = tid >> 3, f = tid & 7;
        #pragma unroll
        for (int it = 0; it < 4; it++) {
            int nn = n + it * 32;
            uint32_t dh = sb + (BS_OFF + BS_BUF + nn * BS_STR + f * 4) * 4;
            cp16(dh, g_eh + (size_t)nn * DIM + KC + f * 4);
            cp16(dh + BN * BS_STR * 4, g_el + (size_t)nn * DIM + KC + f * 4);
        }
    }
    CP_COMMIT();

    for (int i = tid; i < KCODE; i += NT) sm[NE_OFF + i] = g_ne[i];

    CP_WAIT1();
    __syncthreads();

    if (tid < BM) {
        const float* ar = sm + AS_OFF + tid * AS_STR;
        float s = 0.0f;
        #pragma unroll 8
        for (int j = 0; j < DIM / 4; j++) {
            float4 v = *(const float4*)(ar + j * 4);
            s = __fadd_rn(s, __fmul_rn(v.x, v.x));
            s = __fadd_rn(s, __fmul_rn(v.y, v.y));
            s = __fadd_rn(s, __fmul_rn(v.z, v.z));
            s = __fadd_rn(s, __fmul_rn(v.w, v.w));
        }
        sm[NX_OFF + tid] = s;
    }
    __syncthreads();

    float bv[4]  = {3.4e38f, 3.4e38f, 3.4e38f, 3.4e38f};
    float bv2[4] = {3.4e38f, 3.4e38f, 3.4e38f, 3.4e38f};
    int   bi[4]  = {0, 0, 0, 0};
    float nxs[4];
    #pragma unroll
    for (int s = 0; s < 4; s++) nxs[s] = sm[NX_OFF + m0 + (s >> 1) * 16 + (s & 1) * 8 + g];

    const float* arow[4];
    #pragma unroll
    for (int s = 0; s < 4; s++) arow[s] = sm + AS_OFF + (m0 + (s >> 1) * 16 + (s & 1) * 8 + g) * AS_STR;

    int gc = 0;
    for (int ct = 0; ct < NCT; ct++) {
        float acc[2][8][4];
        #pragma unroll
        for (int mt = 0; mt < 2; mt++)
            #pragma unroll
            for (int j = 0; j < 8; j++)
                #pragma unroll
                for (int q = 0; q < 4; q++) acc[mt][j][q] = 0.0f;

        for (int dc = 0; dc < DIM / KC; dc++, gc++) {
            CP_WAIT1();
            __syncthreads();

            const uint32_t* Bh = (const uint32_t*)(sm + BS_OFF + (gc & 1) * BS_BUF);
            const uint32_t* Bl = Bh + BN * BS_STR;
            const int kb = dc * KC;

            #pragma unroll
            for (int kk = 0; kk < 4; kk++) {
                const int k = kb + kk * 8 + tig;
                uint32_t AH[2][4], AL[2][4];
                #pragma unroll
                for (int mt = 0; mt < 2; mt++) {
                    float v0 = arow[mt * 2 + 0][k];
                    float v1 = arow[mt * 2 + 1][k];
                    float v2 = arow[mt * 2 + 0][k + 4];
                    float v3 = arow[mt * 2 + 1][k + 4];
                    AH[mt][0] = tf32_rna(v0); AL[mt][0] = tf32_rna(__fsub_rn(v0, __uint_as_float(AH[mt][0])));
                    AH[mt][1] = tf32_rna(v1); AL[mt][1] = tf32_rna(__fsub_rn(v1, __uint_as_float(AH[mt][1])));
                    AH[mt][2] = tf32_rna(v2); AL[mt][2] = tf32_rna(__fsub_rn(v2, __uint_as_float(AH[mt][2])));
                    AH[mt][3] = tf32_rna(v3); AL[mt][3] = tf32_rna(__fsub_rn(v3, __uint_as_float(AH[mt][3])));
                }
                #pragma unroll
                for (int j = 0; j < 8; j++) {
                    const int nb = (n0w + j * 8 + g) * BS_STR + kk * 8 + tig;
                    uint32_t bh0 = Bh[nb], bh1 = Bh[nb + 4];
                    uint32_t bl0 = Bl[nb], bl1 = Bl[nb + 4];
                    mma8(acc[0][j], AH[0], bh0, bh1);
                    mma8(acc[1][j], AH[1], bh0, bh1);
                    mma8(acc[0][j], AH[0], bl0, bl1);
                    mma8(acc[1][j], AH[1], bl0, bl1);
                    mma8(acc[0][j], AL[0], bh0, bh1);
                    mma8(acc[1][j], AL[1], bh0, bh1);
                }
            }
            __syncthreads();

            if (gc + 2 < NCHT) {
                int gn = gc + 2;
                int ctn = gn >> 3, dcn = gn & 7;
                int n = tid >> 3, f = tid & 7;
                #pragma unroll
                for (int it = 0; it < 4; it++) {
                    int nn = n + it * 32;
                    uint32_t dh = sb + (BS_OFF + (gn & 1) * BS_BUF + nn * BS_STR + f * 4) * 4;
                    size_t src = (size_t)(ctn * BN + nn) * DIM + dcn * KC + f * 4;
                    cp16(dh, g_eh + src);
                    cp16(dh + BN * BS_STR * 4, g_el + src);
                }
            }
            CP_COMMIT();
        }

        // ---- epilogue: distances + running (best, second-best) -------------
        #pragma unroll
        for (int mt = 0; mt < 2; mt++) {
            #pragma unroll
            for (int j = 0; j < 8; j++) {
                const int cbase = ct * BN + n0w + j * 8 + tig * 2;
                float ne0 = sm[NE_OFF + cbase];
                float ne1 = sm[NE_OFF + cbase + 1];
                #pragma unroll
                for (int h = 0; h < 2; h++) {
                    const int s = mt * 2 + h;
                    float t0 = __fadd_rn(nxs[s], ne0);
                    float d0 = __fadd_rn(t0, __fmul_rn(-2.0f, acc[mt][j][h * 2 + 0]));
                    if (d0 < bv[s]) { bv2[s] = bv[s]; bv[s] = d0; bi[s] = cbase; }
                    else if (d0 < bv2[s]) bv2[s] = d0;
                    float t1 = __fadd_rn(nxs[s], ne1);
                    float d1 = __fadd_rn(t1, __fmul_rn(-2.0f, acc[mt][j][h * 2 + 1]));
                    if (d1 < bv[s]) { bv2[s] = bv[s]; bv[s] = d1; bi[s] = cbase + 1; }
                    else if (d1 < bv2[s]) bv2[s] = d1;
                }
            }
        }
    }

    // ---- reduce across the 4 lanes of each mma group -----------------------
    #pragma unroll
    for (int off = 1; off <= 2; off <<= 1) {
        #pragma unroll
        for (int s = 0; s < 4; s++) {
            float ov  = __shfl_xor_sync(0xffffffffu, bv[s], off);
            int   oi  = __shfl_xor_sync(0xffffffffu, bi[s], off);
            float ov2 = __shfl_xor_sync(0xffffffffu, bv2[s], off);
            float loser = fmaxf(bv[s], ov);
            if (ov < bv[s] || (ov == bv[s] && oi < bi[s])) { bv[s] = ov; bi[s] = oi; }
            bv2[s] = fminf(fminf(bv2[s], ov2), loser);
        }
    }
    if (tig == 0) {
        #pragma unroll
        for (int s = 0; s < 4; s++) {
            int row = m0 + (s >> 1) * 16 + (s & 1) * 8 + g;
            sm[RV_OFF + wn * BM + row] = bv[s];
            ((int*)sm)[RI_OFF + wn * BM + row] = bi[s];
            sm[R2_OFF + wn * BM + row] = bv2[s];
        }
    }
    __syncthreads();

    // ---- merge halves, write index, flag marginal rows ---------------------
    if (tid < BM) {
        float v0 = sm[RV_OFF + tid];
        int   i0 = ((int*)sm)[RI_OFF + tid];
        float v1 = sm[RV_OFF + BM + tid];
        int   i1 = ((int*)sm)[RI_OFF + BM + tid];
        float s2 = fminf(sm[R2_OFF + tid], sm[R2_OFF + BM + tid]);
        s2 = fminf(s2, fmaxf(v0, v1));
        float vb = v0; int ib = i0;
        if (v1 < v0 || (v1 == v0 && i1 < i0)) { vb = v1; ib = i1; }
        int r = rbase + tid;
        g_idx[r] = ib;
        if (s2 - vb <= DELTA) {
            int slot = atomicAdd(&g_cnt, 1);
            g_list[slot] = r;
        }
    }
}

// ===========================================================================
// exact repair: R1 bit-exact distance scan for marginal rows
// ===========================================================================
__global__ __launch_bounds__(256)
void k_repair(const float* __restrict__ x, const float* __restrict__ emb) {
    __shared__ float sx[DIM];
    __shared__ float wv[8];
    __shared__ int   wi[8];
    const int tid = threadIdx.x;
    const int cnt = g_cnt;

    for (int li = blockIdx.x; li < cnt; li += gridDim.x) {
        const int row = g_list[li];
        __syncthreads();
        if (tid < DIM) sx[tid] = x[(size_t)row * DIM + tid];
        __syncthreads();

        // nx: exact R1 chain
        float nx = 0.0f;
        #pragma unroll 8
        for (int d = 0; d < DIM; d++) nx = __fadd_rn(nx, __fmul_rn(sx[d], sx[d]));

        float bestv = 3.4e38f;
        int   besti = 0;
        #pragma unroll 1
        for (int cc = 0; cc < KCODE / 256; cc++) {
            int c = cc * 256 + tid;                 // ascending per thread
            const float* e = emb + (size_t)c * DIM;
            float acc = 0.0f;
            #pragma unroll 8
            for (int d = 0; d < DIM; d++) acc = fmaf(sx[d], e[d], acc);
            float t    = __fadd_rn(nx, g_ne[c]);
            float dist = __fadd_rn(t, __fmul_rn(-2.0f, acc));
            if (dist < bestv) { bestv = dist; besti = c; }
        }
        // lexicographic block reduce
        #pragma unroll
        for (int off = 16; off >= 1; off >>= 1) {
            float ov = __shfl_down_sync(0xffffffffu, bestv, off);
            int   oi = __shfl_down_sync(0xffffffffu, besti, off);
            if (ov < bestv || (ov == bestv && oi < besti)) { bestv = ov; besti = oi; }
        }
        if ((tid & 31) == 0) { wv[tid >> 5] = bestv; wi[tid >> 5] = besti; }
        __syncthreads();
        if (tid == 0) {
            float v = wv[0]; int bi = wi[0];
            #pragma unroll
            for (int w = 1; w < 8; w++)
                if (wv[w] < v || (wv[w] == v && wi[w] < bi)) { v = wv[w]; bi = wi[w]; }
            g_idx[row] = bi;
        }
    }
}

// ===========================================================================
// gather + STE output + loss partials; also writes index output
// ===========================================================================
__global__ __launch_bounds__(256)
void k_quant(const float* __restrict__ x, const float* __restrict__ emb,
             float* __restrict__ out, int idx_off) {
    int g   = blockIdx.x * 256 + threadIdx.x;
    int row = g >> 6;
    int c4  = g & 63;
    int idx = g_idx[row];
    float4 q  = reinterpret_cast<const float4*>(emb)[idx * (DIM / 4) + c4];
    float4 xv = reinterpret_cast<const float4*>(x)[g];
    float4 t, o;
    t.x = __fadd_rn(q.x, -xv.x); t.y = __fadd_rn(q.y, -xv.y);
    t.z = __fadd_rn(q.z, -xv.z); t.w = __fadd_rn(q.w, -xv.w);
    o.x = __fadd_rn(xv.x, t.x);  o.y = __fadd_rn(xv.y, t.y);
    o.z = __fadd_rn(xv.z, t.z);  o.w = __fadd_rn(xv.w, t.w);
    reinterpret_cast<float4*>(out)[g] = o;

    if (idx_off >= 0 && g < NROWS) out[idx_off + g] = (float)g_idx[g];

    float s = t.x * t.x + t.y * t.y + t.z * t.z + t.w * t.w;
    #pragma unroll
    for (int off = 16; off >= 1; off >>= 1)
        s += __shfl_down_sync(0xffffffffu, s, off);
    __shared__ float wsum[8];
    int lane = threadIdx.x & 31, warp = threadIdx.x >> 5;
    if (lane == 0) wsum[warp] = s;
    __syncthreads();
    if (threadIdx.x == 0) {
        float tsum = wsum[0];
        #pragma unroll
        for (int w = 1; w < 8; w++) tsum += wsum[w];
        g_part[blockIdx.x] = tsum;
    }
}

__global__ void k_loss(float* __restrict__ out_loss) {
    __shared__ float smr[256];
    int tid = threadIdx.x;
    float s = 0.0f;
    for (int i = tid; i < 16384; i += 256) s += g_part[i];
    smr[tid] = s;
    __syncthreads();
    for (int off = 128; off >= 1; off >>= 1) {
        if (tid < off) smr[tid] += smr[tid + off];
        __syncthreads();
    }
    if (tid == 0) *out_loss = 0.25f * (smr[0] / 16777216.0f);
}

// ===========================================================================
extern "C" void kernel_launch(void* const* d_in, const int* in_sizes, int n_in,
                              void* d_out, int out_size) {
    const float* x   = (const float*)d_in[0];
    const float* emb = (const float*)d_in[1];
    if (n_in >= 2 && in_sizes[0] == KCODE * DIM && in_sizes[1] == NROWS * DIM) {
        const float* t = x; x = emb; emb = t;
    }
    float* out = (float*)d_out;

    int loss_off = -1, idx_off = -1;
    if (out_size >= ND + 1 + NROWS)  { loss_off = ND; idx_off = ND + 1; }
    else if (out_size == ND + NROWS) { idx_off = ND; }
    else if (out_size == ND + 1)     { loss_off = ND; }

    cudaFuncSetAttribute(k_gemm, cudaFuncAttributeMaxDynamicSharedMemorySize, SMEM_BYTES);

    k_ne<<<(KCODE + 255) / 256, 256>>>(emb);
    k_prep<<<KCODE * DIM / 4 / 256, 256>>>(emb);
    k_gemm<<<GRID, NT, SMEM_BYTES>>>(x);
    k_repair<<<256, 256>>>(x, emb);
    k_quant<<<ND / 4 / 256, 256>>>(x, emb, out, idx_off);
    if (loss_off >= 0) k_loss<<<1, 256>>>(out + loss_off);
}